// round 7
// baseline (speedup 1.0000x reference)
#include <cuda_runtime.h>
#include <cstdint>
#include <math.h>

// ===========================================================================
// B=8, S=2048, D=1024 fp32.
//   scores = causal(x x^T / 32); P = softmax(scores); attn = P x; y = attn W^T
// GEMM engine: mma.sync.m16n8k8 TF32. CTA tile 128x256, warp tile 64x64,
// BK=32, 3-stage cp.async pipeline, ldmatrix fragment loads, 1 CTA/SM.
// ===========================================================================

#define BATCH 8
#define SEQ   2048
#define DIM   1024

#define TM 128
#define TN 256
#define CK 32                 // K floats per pipeline chunk
#define LDK 36                // smem row stride in floats (conflict-free)
#define NSTAGE 3
#define A_FLOATS (TM * LDK)               // 4608
#define B_FLOATS (TN * LDK)               // 9216
#define STAGE_FLOATS (A_FLOATS + B_FLOATS)
#define DSMEM_SZ (NSTAGE * STAGE_FLOATS * 4)   // 165888 B

static __device__ float g_scores[(long)BATCH * SEQ * SEQ];
static __device__ float g_xr[(long)BATCH * SEQ * DIM];
static __device__ float g_xT[(long)BATCH * DIM * SEQ];
static __device__ float g_attn[(long)BATCH * SEQ * DIM];
static __device__ float g_Wr[DIM * DIM];

// ---------------------------------------------------------------- helpers --
__device__ __forceinline__ uint32_t smem_u32(const void* p) {
    uint32_t a;
    asm("{ .reg .u64 t; cvta.to.shared.u64 t, %1; cvt.u32.u64 %0, t; }"
        : "=r"(a) : "l"(p));
    return a;
}
__device__ __forceinline__ float tf32r(float x) {
    float y; asm("cvt.rna.tf32.f32 %0, %1;" : "=f"(y) : "f"(x)); return y;
}
__device__ __forceinline__ void cp_async16(uint32_t s, const void* g) {
    asm volatile("cp.async.cg.shared.global [%0], [%1], 16;" :: "r"(s), "l"(g));
}
#define CP_COMMIT() asm volatile("cp.async.commit_group;" ::: "memory")
#define CP_WAIT(n)  asm volatile("cp.async.wait_group %0;" :: "n"(n) : "memory")

__device__ __forceinline__ void mma_tf32(float c[4], const uint32_t a[4], const uint32_t b[2]) {
    asm volatile(
        "mma.sync.aligned.m16n8k8.row.col.f32.tf32.tf32.f32 "
        "{%0,%1,%2,%3}, {%4,%5,%6,%7}, {%8,%9}, {%0,%1,%2,%3};"
        : "+f"(c[0]), "+f"(c[1]), "+f"(c[2]), "+f"(c[3])
        : "r"(a[0]), "r"(a[1]), "r"(a[2]), "r"(a[3]), "r"(b[0]), "r"(b[1]));
}
__device__ __forceinline__ void ldsm4(uint32_t r[4], uint32_t addr) {
    asm volatile("ldmatrix.sync.aligned.m8n8.x4.shared.b16 {%0,%1,%2,%3}, [%4];"
                 : "=r"(r[0]), "=r"(r[1]), "=r"(r[2]), "=r"(r[3]) : "r"(addr));
}

// ---------------------------------------------------------------- GEMM NT --
// C[m,n] = scale * sum_k A[m,k] * B[n,k]
__global__ __launch_bounds__(256, 1) void gemm_nt_mma(
    const float* __restrict__ A, const float* __restrict__ B, float* __restrict__ C,
    int K, int lda, int ldb, int ldc,
    long sA, long sB, long sC,
    float scale, int causal, int klimit, int roundOut)
{
    extern __shared__ float smem[];

    A += (long)blockIdx.z * sA;
    B += (long)blockIdx.z * sB;
    C += (long)blockIdx.z * sC;

    const int m0 = blockIdx.y * TM;
    const int n0 = blockIdx.x * TN;
    if (causal && n0 > m0 + TM - 1) return;
    const int kmax = klimit ? min(K, m0 + TM) : K;
    const int nch  = kmax / CK;

    const int tid   = threadIdx.x;
    const int lane  = tid & 31;
    const int wid   = tid >> 5;
    const int warpM = wid & 1;      // 0..1 -> 64-row slab
    const int warpN = wid >> 1;     // 0..3 -> 64-col slab
    const int qr    = lane >> 2;    // 0..7
    const int qk    = lane & 3;     // 0..3

    const uint32_t sbase = smem_u32(smem);

    // ldmatrix lane addressing (byte offsets inside a stage, kk added later):
    // A frag mf: matrices (r0,c0),(r+8,c0),(r0,c+4),(r+8,c+4); lane l -> matrix l>>3
    const int a_row = warpM * 64 + (((lane >> 3) & 1) << 3) + (lane & 7);
    const int a_col = (lane >> 4) << 2;
    // B pair p (frags 2p,2p+1): matrices (n0..7,c0),(n,c+4),(n+8,c0),(n+8,c+4)
    const int b_row = warpN * 64 + (((lane >> 4) & 1) << 3) + (lane & 7);
    const int b_col = ((lane >> 3) & 1) << 2;
    uint32_t a_off[4], b_off[4];
#pragma unroll
    for (int mf = 0; mf < 4; mf++)
        a_off[mf] = (uint32_t)(((a_row + mf * 16) * LDK + a_col) * 4);
#pragma unroll
    for (int p = 0; p < 4; p++)
        b_off[p] = (uint32_t)((A_FLOATS + (b_row + p * 16) * LDK + b_col) * 4);

    // gmem->smem mapping: 3072 float4 per stage, 12 per thread
    const int gk4 = (tid & 7) << 2;   // 0..28 step 4

    float acc[32][4];
#pragma unroll
    for (int i = 0; i < 32; i++)
#pragma unroll
        for (int j = 0; j < 4; j++) acc[i][j] = 0.f;

    auto load_stage = [&](int s, int c) {
        const uint32_t st = sbase + (uint32_t)(s * STAGE_FLOATS) * 4u;
        const float* gA = A + (long)m0 * lda + c * CK;
        const float* gB = B + (long)n0 * ldb + c * CK;
#pragma unroll
        for (int i = 0; i < 4; i++) {           // A: 128 rows
            int row = (tid >> 3) + i * 32;
            cp_async16(st + (uint32_t)(row * LDK + gk4) * 4u,
                       gA + (long)row * lda + gk4);
        }
#pragma unroll
        for (int i = 0; i < 8; i++) {           // B: 256 rows
            int row = (tid >> 3) + i * 32;
            cp_async16(st + (uint32_t)(A_FLOATS + row * LDK + gk4) * 4u,
                       gB + (long)row * ldb + gk4);
        }
    };

#pragma unroll
    for (int s = 0; s < NSTAGE - 1; s++) {
        if (s < nch) load_stage(s, s);
        CP_COMMIT();
    }

    for (int c = 0; c < nch; c++) {
        CP_WAIT(NSTAGE - 2);
        __syncthreads();

        const int pf = c + NSTAGE - 1;
        if (pf < nch) load_stage(pf % NSTAGE, pf);
        CP_COMMIT();

        const uint32_t st = sbase + (uint32_t)((c % NSTAGE) * STAGE_FLOATS) * 4u;

#pragma unroll
        for (int kk = 0; kk < CK; kk += 8) {
            uint32_t a[4][4], b[4][4];
#pragma unroll
            for (int mf = 0; mf < 4; mf++)
                ldsm4(a[mf], st + a_off[mf] + kk * 4);
#pragma unroll
            for (int p = 0; p < 4; p++)
                ldsm4(b[p], st + b_off[p] + kk * 4);
#pragma unroll
            for (int mf = 0; mf < 4; mf++)
#pragma unroll
                for (int nf = 0; nf < 8; nf++)
                    mma_tf32(acc[mf * 8 + nf], a[mf], &b[nf >> 1][(nf & 1) << 1]);
        }
    }

#pragma unroll
    for (int mf = 0; mf < 4; mf++) {
        const int m = m0 + warpM * 64 + mf * 16 + qr;
#pragma unroll
        for (int nf = 0; nf < 8; nf++) {
            const int n = n0 + warpN * 64 + nf * 8 + 2 * qk;
            float* c0 = acc[mf * 8 + nf];
            float v0 = c0[0] * scale, v1 = c0[1] * scale;
            float v2 = c0[2] * scale, v3 = c0[3] * scale;
            if (roundOut) { v0 = tf32r(v0); v1 = tf32r(v1); v2 = tf32r(v2); v3 = tf32r(v3); }
            *(float2*)&C[(long)m * ldc + n]       = make_float2(v0, v1);
            *(float2*)&C[(long)(m + 8) * ldc + n] = make_float2(v2, v3);
        }
    }
}

// ---------------------------------------------------------------- elementwise
__global__ __launch_bounds__(256) void round_kernel(const float* __restrict__ in,
                                                    float* __restrict__ out, long n4)
{
    long i = (long)blockIdx.x * blockDim.x + threadIdx.x;
    if (i >= n4) return;
    float4 v = ((const float4*)in)[i];
    v.x = tf32r(v.x); v.y = tf32r(v.y); v.z = tf32r(v.z); v.w = tf32r(v.w);
    ((float4*)out)[i] = v;
}

__global__ __launch_bounds__(256) void transpose_round(const float* __restrict__ x,
                                                       float* __restrict__ xT)
{
    __shared__ float t[32][33];
    const int b  = blockIdx.z;
    const int s0 = blockIdx.x * 32;
    const int d0 = blockIdx.y * 32;
    const float* xb = x + (long)b * SEQ * DIM;
    float* ob = xT + (long)b * DIM * SEQ;
    const int tx = threadIdx.x & 31;
    const int tg = threadIdx.x >> 5;
#pragma unroll
    for (int r = 0; r < 4; r++) {
        int row = tg * 4 + r;
        t[row][tx] = xb[(long)(s0 + row) * DIM + d0 + tx];
    }
    __syncthreads();
#pragma unroll
    for (int r = 0; r < 4; r++) {
        int row = tg * 4 + r;
        ob[(long)(d0 + row) * SEQ + s0 + tx] = tf32r(t[tx][row]);
    }
}

// ---------------------------------------------------------------- softmax --
__global__ __launch_bounds__(256) void softmax_kernel(float* __restrict__ scores)
{
    const long row = blockIdx.x;
    const int  q   = (int)(row % SEQ);
    float* p = scores + row * (long)SEQ;
    const int tid = threadIdx.x;
    const int len = q + 1;

    __shared__ float red[8];

    float v[8];
    float m = -1e30f;
#pragma unroll
    for (int j = 0; j < 8; j++) {
        int i = tid + j * 256;
        v[j] = (i < len) ? p[i] : -1e30f;
        m = fmaxf(m, v[j]);
    }
#pragma unroll
    for (int o = 16; o > 0; o >>= 1) m = fmaxf(m, __shfl_xor_sync(0xffffffffu, m, o));
    if ((tid & 31) == 0) red[tid >> 5] = m;
    __syncthreads();
    float m_all = red[0];
#pragma unroll
    for (int w = 1; w < 8; w++) m_all = fmaxf(m_all, red[w]);
    __syncthreads();

    float s = 0.f;
#pragma unroll
    for (int j = 0; j < 8; j++) {
        v[j] = __expf(v[j] - m_all);
        s += v[j];
    }
#pragma unroll
    for (int o = 16; o > 0; o >>= 1) s += __shfl_xor_sync(0xffffffffu, s, o);
    if ((tid & 31) == 0) red[tid >> 5] = s;
    __syncthreads();
    float s_all = 0.f;
#pragma unroll
    for (int w = 0; w < 8; w++) s_all += red[w];
    const float inv = 1.f / s_all;

#pragma unroll
    for (int j = 0; j < 8; j++) {
        int i = tid + j * 256;
        p[i] = (i < len) ? tf32r(v[j] * inv) : 0.f;
    }
}

// ---------------------------------------------------------------------------
extern "C" void kernel_launch(void* const* d_in, const int* in_sizes, int n_in,
                              void* d_out, int out_size)
{
    const float* x = (const float*)d_in[0];
    const float* W = (const float*)d_in[1];
    float* out = (float*)d_out;

    float *scores, *xr, *xT, *attn, *Wr;
    cudaGetSymbolAddress((void**)&scores, g_scores);
    cudaGetSymbolAddress((void**)&xr, g_xr);
    cudaGetSymbolAddress((void**)&xT, g_xT);
    cudaGetSymbolAddress((void**)&attn, g_attn);
    cudaGetSymbolAddress((void**)&Wr, g_Wr);

    cudaFuncSetAttribute(gemm_nt_mma,
                         cudaFuncAttributeMaxDynamicSharedMemorySize, DSMEM_SZ);

    const float scale = 1.0f / 32.0f;
    dim3 blk(256);

    round_kernel<<<((long)BATCH * SEQ * DIM / 4 + 255) / 256, blk>>>(
        x, xr, (long)BATCH * SEQ * DIM / 4);
    round_kernel<<<(DIM * DIM / 4 + 255) / 256, blk>>>(W, Wr, (long)DIM * DIM / 4);
    transpose_round<<<dim3(SEQ / 32, DIM / 32, BATCH), blk>>>(x, xT);

    // 1) scores = scale * x x^T  (causal tiles only)
    gemm_nt_mma<<<dim3(SEQ / TN, SEQ / TM, BATCH), blk, DSMEM_SZ>>>(
        xr, xr, scores, DIM, DIM, DIM, SEQ,
        (long)SEQ * DIM, (long)SEQ * DIM, (long)SEQ * SEQ,
        scale, 1, 0, 0);

    // 2) causal softmax in place
    softmax_kernel<<<BATCH * SEQ, blk>>>(scores);

    // 3) attn = P x  (B = x^T, k-limited)
    gemm_nt_mma<<<dim3(DIM / TN, SEQ / TM, BATCH), blk, DSMEM_SZ>>>(
        scores, xT, attn, SEQ, SEQ, SEQ, DIM,
        (long)SEQ * SEQ, (long)DIM * SEQ, (long)SEQ * DIM,
        1.0f, 0, 1, 1);

    // 4) y = attn W^T
    gemm_nt_mma<<<dim3(DIM / TN, (BATCH * SEQ) / TM, 1), blk, DSMEM_SZ>>>(
        attn, Wr, out, DIM, DIM, DIM, DIM,
        0, 0, 0,
        1.0f, 0, 0, 0);
}

// round 8
// speedup vs baseline: 1.0440x; 1.0440x over previous
#include <cuda_runtime.h>
#include <cstdint>
#include <math.h>

// ===========================================================================
// B=8, S=2048, D=1024 fp32.
//   scores = causal(x x^T / 32); P = softmax(scores); attn = P x; y = attn W^T
// GEMM engine: mma.sync.m16n8k8 TF32. CTA tile 128x256, warp tile 64x64,
// CK=64, 2-stage cp.async pipeline (fewer chunk boundaries), ldmatrix
// fragment loads, 1 CTA/SM.
// ===========================================================================

#define BATCH 8
#define SEQ   2048
#define DIM   1024

#define TM 128
#define TN 256
#define CK 64                 // K floats per pipeline chunk
#define LDK 68                // smem row stride in floats (conflict-free)
#define NSTAGE 2
#define A_FLOATS (TM * LDK)               // 8704
#define B_FLOATS (TN * LDK)               // 17408
#define STAGE_FLOATS (A_FLOATS + B_FLOATS)
#define DSMEM_SZ (NSTAGE * STAGE_FLOATS * 4)   // 208896 B

static __device__ float g_scores[(long)BATCH * SEQ * SEQ];
static __device__ float g_xr[(long)BATCH * SEQ * DIM];
static __device__ float g_xT[(long)BATCH * DIM * SEQ];
static __device__ float g_attn[(long)BATCH * SEQ * DIM];
static __device__ float g_Wr[DIM * DIM];

// ---------------------------------------------------------------- helpers --
__device__ __forceinline__ uint32_t smem_u32(const void* p) {
    uint32_t a;
    asm("{ .reg .u64 t; cvta.to.shared.u64 t, %1; cvt.u32.u64 %0, t; }"
        : "=r"(a) : "l"(p));
    return a;
}
__device__ __forceinline__ float tf32r(float x) {
    float y; asm("cvt.rna.tf32.f32 %0, %1;" : "=f"(y) : "f"(x)); return y;
}
__device__ __forceinline__ void cp_async16(uint32_t s, const void* g) {
    asm volatile("cp.async.cg.shared.global [%0], [%1], 16;" :: "r"(s), "l"(g));
}
#define CP_COMMIT() asm volatile("cp.async.commit_group;" ::: "memory")
#define CP_WAIT(n)  asm volatile("cp.async.wait_group %0;" :: "n"(n) : "memory")

__device__ __forceinline__ void mma_tf32(float c[4], const uint32_t a[4], const uint32_t b[2]) {
    asm volatile(
        "mma.sync.aligned.m16n8k8.row.col.f32.tf32.tf32.f32 "
        "{%0,%1,%2,%3}, {%4,%5,%6,%7}, {%8,%9}, {%0,%1,%2,%3};"
        : "+f"(c[0]), "+f"(c[1]), "+f"(c[2]), "+f"(c[3])
        : "r"(a[0]), "r"(a[1]), "r"(a[2]), "r"(a[3]), "r"(b[0]), "r"(b[1]));
}
__device__ __forceinline__ void ldsm4(uint32_t r[4], uint32_t addr) {
    asm volatile("ldmatrix.sync.aligned.m8n8.x4.shared.b16 {%0,%1,%2,%3}, [%4];"
                 : "=r"(r[0]), "=r"(r[1]), "=r"(r[2]), "=r"(r[3]) : "r"(addr));
}

// ---------------------------------------------------------------- GEMM NT --
// C[m,n] = scale * sum_k A[m,k] * B[n,k]
__global__ __launch_bounds__(256, 1) void gemm_nt_mma(
    const float* __restrict__ A, const float* __restrict__ B, float* __restrict__ C,
    int K, int lda, int ldb, int ldc,
    long sA, long sB, long sC,
    float scale, int causal, int klimit, int roundOut)
{
    extern __shared__ float smem[];

    A += (long)blockIdx.z * sA;
    B += (long)blockIdx.z * sB;
    C += (long)blockIdx.z * sC;

    const int m0 = blockIdx.y * TM;
    const int n0 = blockIdx.x * TN;
    if (causal && n0 > m0 + TM - 1) return;
    const int kmax = klimit ? min(K, m0 + TM) : K;
    const int nch  = kmax / CK;

    const int tid   = threadIdx.x;
    const int lane  = tid & 31;
    const int wid   = tid >> 5;
    const int warpM = wid & 1;      // 0..1 -> 64-row slab
    const int warpN = wid >> 1;     // 0..3 -> 64-col slab
    const int qr    = lane >> 2;    // 0..7
    const int qk    = lane & 3;     // 0..3

    const uint32_t sbase = smem_u32(smem);

    // ldmatrix lane addressing (validated in prior round):
    const int a_row = warpM * 64 + (((lane >> 3) & 1) << 3) + (lane & 7);
    const int a_col = (lane >> 4) << 2;
    const int b_row = warpN * 64 + (((lane >> 4) & 1) << 3) + (lane & 7);
    const int b_col = ((lane >> 3) & 1) << 2;
    uint32_t a_off[4], b_off[4];
#pragma unroll
    for (int mf = 0; mf < 4; mf++)
        a_off[mf] = (uint32_t)(((a_row + mf * 16) * LDK + a_col) * 4);
#pragma unroll
    for (int p = 0; p < 4; p++)
        b_off[p] = (uint32_t)((A_FLOATS + (b_row + p * 16) * LDK + b_col) * 4);

    // gmem->smem: CK=64 -> 16 float4 per row; row = tid>>4 (+16*i), col4 = (tid&15)*4
    const int grow = tid >> 4;
    const int gk4  = (tid & 15) << 2;

    float acc[32][4];
#pragma unroll
    for (int i = 0; i < 32; i++)
#pragma unroll
        for (int j = 0; j < 4; j++) acc[i][j] = 0.f;

    auto load_stage = [&](int s, int c) {
        const uint32_t st = sbase + (uint32_t)(s * STAGE_FLOATS) * 4u;
        const float* gA = A + (long)m0 * lda + c * CK;
        const float* gB = B + (long)n0 * ldb + c * CK;
#pragma unroll
        for (int i = 0; i < 8; i++) {           // A: 128 rows x 16 f4
            int row = grow + i * 16;
            cp_async16(st + (uint32_t)(row * LDK + gk4) * 4u,
                       gA + (long)row * lda + gk4);
        }
#pragma unroll
        for (int i = 0; i < 16; i++) {          // B: 256 rows x 16 f4
            int row = grow + i * 16;
            cp_async16(st + (uint32_t)(A_FLOATS + row * LDK + gk4) * 4u,
                       gB + (long)row * ldb + gk4);
        }
    };

    load_stage(0, 0);
    CP_COMMIT();

    for (int c = 0; c < nch; c++) {
        CP_WAIT(0);
        __syncthreads();

        const int pf = c + 1;
        if (pf < nch) load_stage(pf & 1, pf);
        CP_COMMIT();

        const uint32_t st = sbase + (uint32_t)((c & 1) * STAGE_FLOATS) * 4u;

#pragma unroll
        for (int kk = 0; kk < CK; kk += 8) {
            uint32_t a[4][4], b[4][4];
#pragma unroll
            for (int mf = 0; mf < 4; mf++)
                ldsm4(a[mf], st + a_off[mf] + kk * 4);
#pragma unroll
            for (int p = 0; p < 4; p++)
                ldsm4(b[p], st + b_off[p] + kk * 4);
#pragma unroll
            for (int mf = 0; mf < 4; mf++)
#pragma unroll
                for (int nf = 0; nf < 8; nf++)
                    mma_tf32(acc[mf * 8 + nf], a[mf], &b[nf >> 1][(nf & 1) << 1]);
        }
    }

#pragma unroll
    for (int mf = 0; mf < 4; mf++) {
        const int m = m0 + warpM * 64 + mf * 16 + qr;
#pragma unroll
        for (int nf = 0; nf < 8; nf++) {
            const int n = n0 + warpN * 64 + nf * 8 + 2 * qk;
            float* c0 = acc[mf * 8 + nf];
            float v0 = c0[0] * scale, v1 = c0[1] * scale;
            float v2 = c0[2] * scale, v3 = c0[3] * scale;
            if (roundOut) { v0 = tf32r(v0); v1 = tf32r(v1); v2 = tf32r(v2); v3 = tf32r(v3); }
            *(float2*)&C[(long)m * ldc + n]       = make_float2(v0, v1);
            *(float2*)&C[(long)(m + 8) * ldc + n] = make_float2(v2, v3);
        }
    }
}

// ---------------------------------------------------------------- elementwise
__global__ __launch_bounds__(256) void round_kernel(const float* __restrict__ in,
                                                    float* __restrict__ out, long n4)
{
    long i = (long)blockIdx.x * blockDim.x + threadIdx.x;
    if (i >= n4) return;
    float4 v = ((const float4*)in)[i];
    v.x = tf32r(v.x); v.y = tf32r(v.y); v.z = tf32r(v.z); v.w = tf32r(v.w);
    ((float4*)out)[i] = v;
}

// one pass over x: xr (rounded, same layout) + xT (rounded transpose)
__global__ __launch_bounds__(256) void round_and_transpose(
    const float* __restrict__ x, float* __restrict__ xr, float* __restrict__ xT)
{
    __shared__ float t[32][33];
    const int b  = blockIdx.z;
    const int s0 = blockIdx.x * 32;
    const int d0 = blockIdx.y * 32;
    const float* xb = x + (long)b * SEQ * DIM;
    float* xrb = xr + (long)b * SEQ * DIM;
    float* xTb = xT + (long)b * DIM * SEQ;
    const int tx = threadIdx.x & 31;
    const int tg = threadIdx.x >> 5;
#pragma unroll
    for (int r = 0; r < 4; r++) {
        int row = tg * 4 + r;
        float v = tf32r(xb[(long)(s0 + row) * DIM + d0 + tx]);
        t[row][tx] = v;
        xrb[(long)(s0 + row) * DIM + d0 + tx] = v;
    }
    __syncthreads();
#pragma unroll
    for (int r = 0; r < 4; r++) {
        int row = tg * 4 + r;
        xTb[(long)(d0 + row) * SEQ + s0 + tx] = t[tx][row];
    }
}

// ---------------------------------------------------------------- softmax --
// in-place causal softmax; writes only columns < roundUp(q+1,128) (the PV
// GEMM k-limits to that boundary, so farther columns are never read).
__global__ __launch_bounds__(256) void softmax_kernel(float* __restrict__ scores)
{
    const long row = blockIdx.x;
    const int  q   = (int)(row % SEQ);
    float* p = scores + row * (long)SEQ;
    const int tid  = threadIdx.x;
    const int len  = q + 1;
    const int lenR = ((q >> 7) + 1) << 7;   // write bound

    __shared__ float red[8];

    float v[8];
    float m = -1e30f;
#pragma unroll
    for (int j = 0; j < 8; j++) {
        int i = tid + j * 256;
        v[j] = (i < len) ? p[i] : -1e30f;
        m = fmaxf(m, v[j]);
    }
#pragma unroll
    for (int o = 16; o > 0; o >>= 1) m = fmaxf(m, __shfl_xor_sync(0xffffffffu, m, o));
    if ((tid & 31) == 0) red[tid >> 5] = m;
    __syncthreads();
    float m_all = red[0];
#pragma unroll
    for (int w = 1; w < 8; w++) m_all = fmaxf(m_all, red[w]);
    __syncthreads();

    float s = 0.f;
#pragma unroll
    for (int j = 0; j < 8; j++) {
        v[j] = __expf(v[j] - m_all);
        s += v[j];
    }
#pragma unroll
    for (int o = 16; o > 0; o >>= 1) s += __shfl_xor_sync(0xffffffffu, s, o);
    if ((tid & 31) == 0) red[tid >> 5] = s;
    __syncthreads();
    float s_all = 0.f;
#pragma unroll
    for (int w = 0; w < 8; w++) s_all += red[w];
    const float inv = 1.f / s_all;

#pragma unroll
    for (int j = 0; j < 8; j++) {
        int i = tid + j * 256;
        if (i < lenR) p[i] = (i < len) ? tf32r(v[j] * inv) : 0.f;
    }
}

// ---------------------------------------------------------------------------
extern "C" void kernel_launch(void* const* d_in, const int* in_sizes, int n_in,
                              void* d_out, int out_size)
{
    const float* x = (const float*)d_in[0];
    const float* W = (const float*)d_in[1];
    float* out = (float*)d_out;

    float *scores, *xr, *xT, *attn, *Wr;
    cudaGetSymbolAddress((void**)&scores, g_scores);
    cudaGetSymbolAddress((void**)&xr, g_xr);
    cudaGetSymbolAddress((void**)&xT, g_xT);
    cudaGetSymbolAddress((void**)&attn, g_attn);
    cudaGetSymbolAddress((void**)&Wr, g_Wr);

    cudaFuncSetAttribute(gemm_nt_mma,
                         cudaFuncAttributeMaxDynamicSharedMemorySize, DSMEM_SZ);

    const float scale = 1.0f / 32.0f;
    dim3 blk(256);

    round_and_transpose<<<dim3(SEQ / 32, DIM / 32, BATCH), blk>>>(x, xr, xT);
    round_kernel<<<(DIM * DIM / 4 + 255) / 256, blk>>>(W, Wr, (long)DIM * DIM / 4);

    // 1) scores = scale * x x^T  (causal tiles only)
    gemm_nt_mma<<<dim3(SEQ / TN, SEQ / TM, BATCH), blk, DSMEM_SZ>>>(
        xr, xr, scores, DIM, DIM, DIM, SEQ,
        (long)SEQ * DIM, (long)SEQ * DIM, (long)SEQ * SEQ,
        scale, 1, 0, 0);

    // 2) causal softmax in place
    softmax_kernel<<<BATCH * SEQ, blk>>>(scores);

    // 3) attn = P x  (B = x^T, k-limited)
    gemm_nt_mma<<<dim3(DIM / TN, SEQ / TM, BATCH), blk, DSMEM_SZ>>>(
        scores, xT, attn, SEQ, SEQ, SEQ, DIM,
        (long)SEQ * SEQ, (long)DIM * SEQ, (long)SEQ * DIM,
        1.0f, 0, 1, 1);

    // 4) y = attn W^T
    gemm_nt_mma<<<dim3(DIM / TN, (BATCH * SEQ) / TM, 1), blk, DSMEM_SZ>>>(
        attn, Wr, out, DIM, DIM, DIM, DIM,
        0, 0, 0,
        1.0f, 0, 0, 0);
}

// round 9
// speedup vs baseline: 1.2484x; 1.1958x over previous
#include <cuda_runtime.h>
#include <cuda_fp16.h>
#include <cstdint>
#include <math.h>

// ===========================================================================
// B=8, S=2048, D=1024 fp32.
//   scores = causal(x x^T / 32); P = softmax(scores); attn = P x; y = attn W^T
// GEMM engine: mma.sync.m16n8k16 FP16 (same 10-bit mantissa as tf32, 2x rate,
// half the operand bytes). CTA tile 128x128, 4 warps x 64x64, CK=64 halves,
// 3-stage cp.async, ldmatrix b16 fragments, 2 CTAs/SM.
// ===========================================================================

#define BATCH 8
#define SEQ   2048
#define DIM   1024

#define TM 128
#define TN 128
#define CKH 64                 // halves per chunk (128 B rows)
#define LDH 72                 // smem row stride in halves (144 B, conflict-free)
#define NSTAGE 3
#define A_BYTES (TM * LDH * 2)            // 18432
#define B_BYTES (TN * LDH * 2)            // 18432
#define STAGE_BYTES (A_BYTES + B_BYTES)   // 36864
#define DSMEM_SZ (NSTAGE * STAGE_BYTES)   // 110592 B  (x2 CTAs = 221 KB)

static __device__ float  g_scores[(long)BATCH * SEQ * SEQ];  // fp32 scores
static __device__ __half g_Ph[(long)BATCH * SEQ * SEQ];      // fp16 P
static __device__ __half g_xh[(long)BATCH * SEQ * DIM];      // fp16 x
static __device__ __half g_xTh[(long)BATCH * DIM * SEQ];     // fp16 x^T
static __device__ __half g_attnh[(long)BATCH * SEQ * DIM];   // fp16 attn
static __device__ __half g_Wh[DIM * DIM];                    // fp16 W

// ---------------------------------------------------------------- helpers --
__device__ __forceinline__ uint32_t smem_u32(const void* p) {
    uint32_t a;
    asm("{ .reg .u64 t; cvta.to.shared.u64 t, %1; cvt.u32.u64 %0, t; }"
        : "=r"(a) : "l"(p));
    return a;
}
__device__ __forceinline__ void cp_async16(uint32_t s, const void* g) {
    asm volatile("cp.async.cg.shared.global [%0], [%1], 16;" :: "r"(s), "l"(g));
}
#define CP_COMMIT() asm volatile("cp.async.commit_group;" ::: "memory")
#define CP_WAIT(n)  asm volatile("cp.async.wait_group %0;" :: "n"(n) : "memory")

__device__ __forceinline__ void mma_f16(float c[4], const uint32_t a[4], const uint32_t b[2]) {
    asm volatile(
        "mma.sync.aligned.m16n8k16.row.col.f32.f16.f16.f32 "
        "{%0,%1,%2,%3}, {%4,%5,%6,%7}, {%8,%9}, {%0,%1,%2,%3};"
        : "+f"(c[0]), "+f"(c[1]), "+f"(c[2]), "+f"(c[3])
        : "r"(a[0]), "r"(a[1]), "r"(a[2]), "r"(a[3]), "r"(b[0]), "r"(b[1]));
}
__device__ __forceinline__ void ldsm4(uint32_t r[4], uint32_t addr) {
    asm volatile("ldmatrix.sync.aligned.m8n8.x4.shared.b16 {%0,%1,%2,%3}, [%4];"
                 : "=r"(r[0]), "=r"(r[1]), "=r"(r[2]), "=r"(r[3]) : "r"(addr));
}

// ---------------------------------------------------------------- GEMM NT --
// C[m,n] = scale * sum_k A[m,k] * B[n,k]   (A,B fp16 K-contiguous)
__global__ __launch_bounds__(128, 2) void gemm_h(
    const __half* __restrict__ A, const __half* __restrict__ B, void* __restrict__ Cv,
    int K, int lda, int ldb, int ldc,
    long sA, long sB, long sC,
    float scale, int causal, int klimit, int outHalf)
{
    extern __shared__ char smem[];

    A += (long)blockIdx.z * sA;
    B += (long)blockIdx.z * sB;

    const int m0 = blockIdx.y * TM;
    const int n0 = blockIdx.x * TN;
    if (causal && n0 > m0 + TM - 1) return;
    const int kmax = klimit ? min(K, m0 + TM) : K;
    const int nch  = kmax / CKH;

    const int tid   = threadIdx.x;
    const int lane  = tid & 31;
    const int wid   = tid >> 5;            // 0..3
    const int warpM = wid & 1;             // 2 x 2 warp grid, 64x64 each
    const int warpN = wid >> 1;
    const int qr    = lane >> 2;
    const int qk    = lane & 3;

    const uint32_t sbase = smem_u32(smem);

    // ldmatrix lane addressing (byte offsets within stage; kk*2 added later)
    const int a_row_l = (((lane >> 3) & 1) << 3) + (lane & 7);
    const int a_kh    = ((lane >> 4) & 1) << 3;   // halves
    const int b_row_l = (((lane >> 4) & 1) << 3) + (lane & 7);
    const int b_kh    = ((lane >> 3) & 1) << 3;
    uint32_t a_off[4], b_off[4];
#pragma unroll
    for (int mf = 0; mf < 4; mf++)
        a_off[mf] = (uint32_t)((warpM * 64 + mf * 16 + a_row_l) * (LDH * 2) + a_kh * 2);
#pragma unroll
    for (int p = 0; p < 4; p++)
        b_off[p] = (uint32_t)(A_BYTES + (warpN * 64 + p * 16 + b_row_l) * (LDH * 2) + b_kh * 2);

    float acc[32][4];
#pragma unroll
    for (int i = 0; i < 32; i++)
#pragma unroll
        for (int j = 0; j < 4; j++) acc[i][j] = 0.f;

    // gmem->smem: per stage A and B each 128 rows x 8 x 16B chunks
    auto load_stage = [&](int s, int c) {
        const uint32_t st = sbase + (uint32_t)(s * STAGE_BYTES);
        const char* gA = (const char*)(A + (long)m0 * lda + c * CKH);
        const char* gB = (const char*)(B + (long)n0 * ldb + c * CKH);
#pragma unroll
        for (int i = 0; i < 8; i++) {
            int idx = tid + i * 128;         // 0..1023
            int row = idx >> 3;
            int ch  = (idx & 7) << 4;        // byte offset in row
            cp_async16(st + (uint32_t)(row * (LDH * 2)) + ch,
                       gA + (long)row * lda * 2 + ch);
        }
#pragma unroll
        for (int i = 0; i < 8; i++) {
            int idx = tid + i * 128;
            int row = idx >> 3;
            int ch  = (idx & 7) << 4;
            cp_async16(st + (uint32_t)(A_BYTES + row * (LDH * 2)) + ch,
                       gB + (long)row * ldb * 2 + ch);
        }
    };

#pragma unroll
    for (int s = 0; s < NSTAGE - 1; s++) {
        if (s < nch) load_stage(s, s);
        CP_COMMIT();
    }

    for (int c = 0; c < nch; c++) {
        CP_WAIT(NSTAGE - 2);
        __syncthreads();

        const int pf = c + NSTAGE - 1;
        if (pf < nch) load_stage(pf % NSTAGE, pf);
        CP_COMMIT();

        const uint32_t st = sbase + (uint32_t)((c % NSTAGE) * STAGE_BYTES);

#pragma unroll
        for (int kk = 0; kk < CKH; kk += 16) {
            uint32_t a[4][4], b[4][4];
#pragma unroll
            for (int mf = 0; mf < 4; mf++)
                ldsm4(a[mf], st + a_off[mf] + kk * 2);
#pragma unroll
            for (int p = 0; p < 4; p++)
                ldsm4(b[p], st + b_off[p] + kk * 2);
#pragma unroll
            for (int mf = 0; mf < 4; mf++)
#pragma unroll
                for (int nf = 0; nf < 8; nf++)
                    mma_f16(acc[mf * 8 + nf], a[mf], &b[nf >> 1][(nf & 1) << 1]);
        }
    }

    // epilogue
    if (outHalf) {
        __half* C = (__half*)Cv + (long)blockIdx.z * sC;
#pragma unroll
        for (int mf = 0; mf < 4; mf++) {
            const int m = m0 + warpM * 64 + mf * 16 + qr;
#pragma unroll
            for (int nf = 0; nf < 8; nf++) {
                const int n = n0 + warpN * 64 + nf * 8 + 2 * qk;
                float* c0 = acc[mf * 8 + nf];
                *(__half2*)&C[(long)m * ldc + n] =
                    __floats2half2_rn(c0[0] * scale, c0[1] * scale);
                *(__half2*)&C[(long)(m + 8) * ldc + n] =
                    __floats2half2_rn(c0[2] * scale, c0[3] * scale);
            }
        }
    } else {
        float* C = (float*)Cv + (long)blockIdx.z * sC;
#pragma unroll
        for (int mf = 0; mf < 4; mf++) {
            const int m = m0 + warpM * 64 + mf * 16 + qr;
#pragma unroll
            for (int nf = 0; nf < 8; nf++) {
                const int n = n0 + warpN * 64 + nf * 8 + 2 * qk;
                float* c0 = acc[mf * 8 + nf];
                *(float2*)&C[(long)m * ldc + n] =
                    make_float2(c0[0] * scale, c0[1] * scale);
                *(float2*)&C[(long)(m + 8) * ldc + n] =
                    make_float2(c0[2] * scale, c0[3] * scale);
            }
        }
    }
}

// ---------------------------------------------------------------- prep -----
// x fp32 -> xh (same layout fp16) + xTh (transposed fp16)
__global__ __launch_bounds__(256) void conv_x(
    const float* __restrict__ x, __half* __restrict__ xh, __half* __restrict__ xT)
{
    __shared__ float t[32][33];
    const int b  = blockIdx.z;
    const int s0 = blockIdx.x * 32;
    const int d0 = blockIdx.y * 32;
    const float* xb = x + (long)b * SEQ * DIM;
    __half* xhb = xh + (long)b * SEQ * DIM;
    __half* xTb = xT + (long)b * DIM * SEQ;
    const int tx = threadIdx.x & 31;
    const int tg = threadIdx.x >> 5;
#pragma unroll
    for (int r = 0; r < 4; r++) {
        int row = tg * 4 + r;
        float v = xb[(long)(s0 + row) * DIM + d0 + tx];
        t[row][tx] = v;
        xhb[(long)(s0 + row) * DIM + d0 + tx] = __float2half_rn(v);
    }
    __syncthreads();
#pragma unroll
    for (int r = 0; r < 4; r++) {
        int row = tg * 4 + r;
        xTb[(long)(d0 + row) * SEQ + s0 + tx] = __float2half_rn(t[tx][row]);
    }
}

__global__ __launch_bounds__(256) void conv_W(const float* __restrict__ W,
                                              __half* __restrict__ Wh, long n4)
{
    long i = (long)blockIdx.x * blockDim.x + threadIdx.x;
    if (i >= n4) return;
    float4 v = ((const float4*)W)[i];
    __half2* o = (__half2*)Wh + i * 2;
    o[0] = __floats2half2_rn(v.x, v.y);
    o[1] = __floats2half2_rn(v.z, v.w);
}

// ---------------------------------------------------------------- softmax --
// causal softmax: reads fp32 scores, writes fp16 P (cols < roundUp(q+1,128))
__global__ __launch_bounds__(256) void softmax_kernel(
    const float* __restrict__ scores, __half* __restrict__ P)
{
    const long row = blockIdx.x;
    const int  q   = (int)(row % SEQ);
    const float* p = scores + row * (long)SEQ;
    __half* po = P + row * (long)SEQ;
    const int tid  = threadIdx.x;
    const int len  = q + 1;
    const int lenR = ((q >> 7) + 1) << 7;

    __shared__ float red[8];

    float v[8];
    float m = -1e30f;
#pragma unroll
    for (int j = 0; j < 8; j++) {
        int i = tid + j * 256;
        v[j] = (i < len) ? p[i] : -1e30f;
        m = fmaxf(m, v[j]);
    }
#pragma unroll
    for (int o = 16; o > 0; o >>= 1) m = fmaxf(m, __shfl_xor_sync(0xffffffffu, m, o));
    if ((tid & 31) == 0) red[tid >> 5] = m;
    __syncthreads();
    float m_all = red[0];
#pragma unroll
    for (int w = 1; w < 8; w++) m_all = fmaxf(m_all, red[w]);
    __syncthreads();

    float s = 0.f;
#pragma unroll
    for (int j = 0; j < 8; j++) {
        v[j] = __expf(v[j] - m_all);
        s += v[j];
    }
#pragma unroll
    for (int o = 16; o > 0; o >>= 1) s += __shfl_xor_sync(0xffffffffu, s, o);
    if ((tid & 31) == 0) red[tid >> 5] = s;
    __syncthreads();
    float s_all = 0.f;
#pragma unroll
    for (int w = 0; w < 8; w++) s_all += red[w];
    const float inv = 1.f / s_all;

#pragma unroll
    for (int j = 0; j < 8; j++) {
        int i = tid + j * 256;
        if (i < lenR)
            po[i] = __float2half_rn((i < len) ? v[j] * inv : 0.f);
    }
}

// ---------------------------------------------------------------------------
extern "C" void kernel_launch(void* const* d_in, const int* in_sizes, int n_in,
                              void* d_out, int out_size)
{
    const float* x = (const float*)d_in[0];
    const float* W = (const float*)d_in[1];
    float* out = (float*)d_out;

    float *scores;
    __half *Ph, *xh, *xTh, *attnh, *Wh;
    cudaGetSymbolAddress((void**)&scores, g_scores);
    cudaGetSymbolAddress((void**)&Ph, g_Ph);
    cudaGetSymbolAddress((void**)&xh, g_xh);
    cudaGetSymbolAddress((void**)&xTh, g_xTh);
    cudaGetSymbolAddress((void**)&attnh, g_attnh);
    cudaGetSymbolAddress((void**)&Wh, g_Wh);

    cudaFuncSetAttribute(gemm_h,
                         cudaFuncAttributeMaxDynamicSharedMemorySize, DSMEM_SZ);

    const float scale = 1.0f / 32.0f;

    conv_x<<<dim3(SEQ / 32, DIM / 32, BATCH), 256>>>(x, xh, xTh);
    conv_W<<<(DIM * DIM / 4 + 255) / 256, 256>>>(W, Wh, (long)DIM * DIM / 4);

    // 1) scores = scale * x x^T  (fp32 out, causal tiles only)
    gemm_h<<<dim3(SEQ / TN, SEQ / TM, BATCH), 128, DSMEM_SZ>>>(
        xh, xh, scores, DIM, DIM, DIM, SEQ,
        (long)SEQ * DIM, (long)SEQ * DIM, (long)SEQ * SEQ,
        scale, 1, 0, 0);

    // 2) causal softmax -> fp16 P
    softmax_kernel<<<BATCH * SEQ, 256>>>(scores, Ph);

    // 3) attn = P x  (fp16 out, k-limited)
    gemm_h<<<dim3(DIM / TN, SEQ / TM, BATCH), 128, DSMEM_SZ>>>(
        Ph, xTh, attnh, SEQ, SEQ, SEQ, DIM,
        (long)SEQ * SEQ, (long)DIM * SEQ, (long)SEQ * DIM,
        1.0f, 0, 1, 1);

    // 4) y = attn W^T  (fp32 out, M = B*S flattened)
    gemm_h<<<dim3(DIM / TN, (BATCH * SEQ) / TM, 1), 128, DSMEM_SZ>>>(
        attnh, Wh, out, DIM, DIM, DIM, DIM,
        0, 0, 0,
        1.0f, 0, 0, 0);
}

// round 10
// speedup vs baseline: 2.0201x; 1.6182x over previous
#include <cuda_runtime.h>
#include <cuda_fp16.h>
#include <cstdint>
#include <math.h>

// ===========================================================================
// B=8, S=2048, D=1024 fp32.
//   scores = causal(x x^T / 32); P = softmax(scores); attn = P x; y = attn W^T
// GEMM engine: mma.sync.m16n8k16 FP16, CTA tile 128x128 (4 warps x 64x64),
// CKH=32, 4-stage cp.async pipeline, ldmatrix b16 fragments, 2 CTAs/SM.
// Scores kept fp16 end-to-end.
// ===========================================================================

#define BATCH 8
#define SEQ   2048
#define DIM   1024

#define TM 128
#define TN 128
#define CKH 32                 // halves per chunk (64 B rows)
#define LDH 40                 // smem row stride in halves (80 B, conflict-free)
#define NSTAGE 4
#define A_BYTES (TM * LDH * 2)            // 10240
#define B_BYTES (TN * LDH * 2)            // 10240
#define STAGE_BYTES (A_BYTES + B_BYTES)   // 20480
#define DSMEM_SZ (NSTAGE * STAGE_BYTES)   // 81920 B (x2 CTAs = 160 KB)

static __device__ __half g_scoresh[(long)BATCH * SEQ * SEQ]; // fp16 scores / P
static __device__ __half g_Ph[(long)BATCH * SEQ * SEQ];      // fp16 P
static __device__ __half g_xh[(long)BATCH * SEQ * DIM];      // fp16 x
static __device__ __half g_xTh[(long)BATCH * DIM * SEQ];     // fp16 x^T
static __device__ __half g_attnh[(long)BATCH * SEQ * DIM];   // fp16 attn
static __device__ __half g_Wh[DIM * DIM];                    // fp16 W

// ---------------------------------------------------------------- helpers --
__device__ __forceinline__ uint32_t smem_u32(const void* p) {
    uint32_t a;
    asm("{ .reg .u64 t; cvta.to.shared.u64 t, %1; cvt.u32.u64 %0, t; }"
        : "=r"(a) : "l"(p));
    return a;
}
__device__ __forceinline__ void cp_async16(uint32_t s, const void* g) {
    asm volatile("cp.async.cg.shared.global [%0], [%1], 16;" :: "r"(s), "l"(g));
}
#define CP_COMMIT() asm volatile("cp.async.commit_group;" ::: "memory")
#define CP_WAIT(n)  asm volatile("cp.async.wait_group %0;" :: "n"(n) : "memory")

__device__ __forceinline__ void mma_f16(float c[4], const uint32_t a[4], const uint32_t b[2]) {
    asm volatile(
        "mma.sync.aligned.m16n8k16.row.col.f32.f16.f16.f32 "
        "{%0,%1,%2,%3}, {%4,%5,%6,%7}, {%8,%9}, {%0,%1,%2,%3};"
        : "+f"(c[0]), "+f"(c[1]), "+f"(c[2]), "+f"(c[3])
        : "r"(a[0]), "r"(a[1]), "r"(a[2]), "r"(a[3]), "r"(b[0]), "r"(b[1]));
}
__device__ __forceinline__ void ldsm4(uint32_t r[4], uint32_t addr) {
    asm volatile("ldmatrix.sync.aligned.m8n8.x4.shared.b16 {%0,%1,%2,%3}, [%4];"
                 : "=r"(r[0]), "=r"(r[1]), "=r"(r[2]), "=r"(r[3]) : "r"(addr));
}

// ---------------------------------------------------------------- GEMM NT --
// C[m,n] = scale * sum_k A[m,k] * B[n,k]   (A,B fp16 K-contiguous)
__global__ __launch_bounds__(128, 2) void gemm_h(
    const __half* __restrict__ A, const __half* __restrict__ B, void* __restrict__ Cv,
    int K, int lda, int ldb, int ldc,
    long sA, long sB, long sC,
    float scale, int causal, int klimit, int outHalf)
{
    extern __shared__ char smem[];

    A += (long)blockIdx.z * sA;
    B += (long)blockIdx.z * sB;

    const int m0 = blockIdx.y * TM;
    const int n0 = blockIdx.x * TN;
    if (causal && n0 > m0 + TM - 1) return;
    const int kmax = klimit ? min(K, m0 + TM) : K;
    const int nch  = kmax / CKH;

    const int tid   = threadIdx.x;
    const int lane  = tid & 31;
    const int wid   = tid >> 5;            // 0..3
    const int warpM = wid & 1;
    const int warpN = wid >> 1;
    const int qr    = lane >> 2;
    const int qk    = lane & 3;

    const uint32_t sbase = smem_u32(smem);

    // ldmatrix lane addressing (validated in Round 9)
    const int a_row_l = (((lane >> 3) & 1) << 3) + (lane & 7);
    const int a_kh    = ((lane >> 4) & 1) << 3;
    const int b_row_l = (((lane >> 4) & 1) << 3) + (lane & 7);
    const int b_kh    = ((lane >> 3) & 1) << 3;
    uint32_t a_off[4], b_off[4];
#pragma unroll
    for (int mf = 0; mf < 4; mf++)
        a_off[mf] = (uint32_t)((warpM * 64 + mf * 16 + a_row_l) * (LDH * 2) + a_kh * 2);
#pragma unroll
    for (int p = 0; p < 4; p++)
        b_off[p] = (uint32_t)(A_BYTES + (warpN * 64 + p * 16 + b_row_l) * (LDH * 2) + b_kh * 2);

    float acc[32][4];
#pragma unroll
    for (int i = 0; i < 32; i++)
#pragma unroll
        for (int j = 0; j < 4; j++) acc[i][j] = 0.f;

    // gmem->smem: per stage A and B each 128 rows x 4 x 16B chunks (512 cp each)
    auto load_stage = [&](int s, int c) {
        const uint32_t st = sbase + (uint32_t)(s * STAGE_BYTES);
        const char* gA = (const char*)(A + (long)m0 * lda + c * CKH);
        const char* gB = (const char*)(B + (long)n0 * ldb + c * CKH);
#pragma unroll
        for (int i = 0; i < 4; i++) {
            int idx = tid + i * 128;         // 0..511
            int row = idx >> 2;
            int ch  = (idx & 3) << 4;
            cp_async16(st + (uint32_t)(row * (LDH * 2)) + ch,
                       gA + (long)row * lda * 2 + ch);
        }
#pragma unroll
        for (int i = 0; i < 4; i++) {
            int idx = tid + i * 128;
            int row = idx >> 2;
            int ch  = (idx & 3) << 4;
            cp_async16(st + (uint32_t)(A_BYTES + row * (LDH * 2)) + ch,
                       gB + (long)row * ldb * 2 + ch);
        }
    };

#pragma unroll
    for (int s = 0; s < NSTAGE - 1; s++) {
        if (s < nch) load_stage(s, s);
        CP_COMMIT();
    }

    for (int c = 0; c < nch; c++) {
        CP_WAIT(NSTAGE - 2);
        __syncthreads();

        const int pf = c + NSTAGE - 1;
        if (pf < nch) load_stage(pf % NSTAGE, pf);
        CP_COMMIT();

        const uint32_t st = sbase + (uint32_t)((c % NSTAGE) * STAGE_BYTES);

#pragma unroll
        for (int kk = 0; kk < CKH; kk += 16) {
            uint32_t a[4][4], b[4][4];
#pragma unroll
            for (int mf = 0; mf < 4; mf++)
                ldsm4(a[mf], st + a_off[mf] + kk * 2);
#pragma unroll
            for (int p = 0; p < 4; p++)
                ldsm4(b[p], st + b_off[p] + kk * 2);
#pragma unroll
            for (int mf = 0; mf < 4; mf++)
#pragma unroll
                for (int nf = 0; nf < 8; nf++)
                    mma_f16(acc[mf * 8 + nf], a[mf], &b[nf >> 1][(nf & 1) << 1]);
        }
    }

    // epilogue
    if (outHalf) {
        __half* C = (__half*)Cv + (long)blockIdx.z * sC;
#pragma unroll
        for (int mf = 0; mf < 4; mf++) {
            const int m = m0 + warpM * 64 + mf * 16 + qr;
#pragma unroll
            for (int nf = 0; nf < 8; nf++) {
                const int n = n0 + warpN * 64 + nf * 8 + 2 * qk;
                float* c0 = acc[mf * 8 + nf];
                *(__half2*)&C[(long)m * ldc + n] =
                    __floats2half2_rn(c0[0] * scale, c0[1] * scale);
                *(__half2*)&C[(long)(m + 8) * ldc + n] =
                    __floats2half2_rn(c0[2] * scale, c0[3] * scale);
            }
        }
    } else {
        float* C = (float*)Cv + (long)blockIdx.z * sC;
#pragma unroll
        for (int mf = 0; mf < 4; mf++) {
            const int m = m0 + warpM * 64 + mf * 16 + qr;
#pragma unroll
            for (int nf = 0; nf < 8; nf++) {
                const int n = n0 + warpN * 64 + nf * 8 + 2 * qk;
                float* c0 = acc[mf * 8 + nf];
                *(float2*)&C[(long)m * ldc + n] =
                    make_float2(c0[0] * scale, c0[1] * scale);
                *(float2*)&C[(long)(m + 8) * ldc + n] =
                    make_float2(c0[2] * scale, c0[3] * scale);
            }
        }
    }
}

// ---------------------------------------------------------------- prep -----
__global__ __launch_bounds__(256) void conv_x(
    const float* __restrict__ x, __half* __restrict__ xh, __half* __restrict__ xT)
{
    __shared__ float t[32][33];
    const int b  = blockIdx.z;
    const int s0 = blockIdx.x * 32;
    const int d0 = blockIdx.y * 32;
    const float* xb = x + (long)b * SEQ * DIM;
    __half* xhb = xh + (long)b * SEQ * DIM;
    __half* xTb = xT + (long)b * DIM * SEQ;
    const int tx = threadIdx.x & 31;
    const int tg = threadIdx.x >> 5;
#pragma unroll
    for (int r = 0; r < 4; r++) {
        int row = tg * 4 + r;
        float v = xb[(long)(s0 + row) * DIM + d0 + tx];
        t[row][tx] = v;
        xhb[(long)(s0 + row) * DIM + d0 + tx] = __float2half_rn(v);
    }
    __syncthreads();
#pragma unroll
    for (int r = 0; r < 4; r++) {
        int row = tg * 4 + r;
        xTb[(long)(d0 + row) * SEQ + s0 + tx] = __float2half_rn(t[tx][row]);
    }
}

__global__ __launch_bounds__(256) void conv_W(const float* __restrict__ W,
                                              __half* __restrict__ Wh, long n4)
{
    long i = (long)blockIdx.x * blockDim.x + threadIdx.x;
    if (i >= n4) return;
    float4 v = ((const float4*)W)[i];
    __half2* o = (__half2*)Wh + i * 2;
    o[0] = __floats2half2_rn(v.x, v.y);
    o[1] = __floats2half2_rn(v.z, v.w);
}

// ---------------------------------------------------------------- softmax --
// causal softmax: fp16 scores in, fp16 P out (cols < roundUp(q+1,128))
__global__ __launch_bounds__(256) void softmax_kernel(
    const __half* __restrict__ scores, __half* __restrict__ P)
{
    const long row = blockIdx.x;
    const int  q   = (int)(row % SEQ);
    const __half* p = scores + row * (long)SEQ;
    __half* po = P + row * (long)SEQ;
    const int tid  = threadIdx.x;
    const int len  = q + 1;
    const int lenR = ((q >> 7) + 1) << 7;

    __shared__ float red[8];

    float v[8];
    float m = -1e30f;
#pragma unroll
    for (int j = 0; j < 8; j++) {
        int i = tid + j * 256;
        v[j] = (i < len) ? __half2float(p[i]) : -1e30f;
        m = fmaxf(m, v[j]);
    }
#pragma unroll
    for (int o = 16; o > 0; o >>= 1) m = fmaxf(m, __shfl_xor_sync(0xffffffffu, m, o));
    if ((tid & 31) == 0) red[tid >> 5] = m;
    __syncthreads();
    float m_all = red[0];
#pragma unroll
    for (int w = 1; w < 8; w++) m_all = fmaxf(m_all, red[w]);
    __syncthreads();

    float s = 0.f;
#pragma unroll
    for (int j = 0; j < 8; j++) {
        v[j] = __expf(v[j] - m_all);
        s += v[j];
    }
#pragma unroll
    for (int o = 16; o > 0; o >>= 1) s += __shfl_xor_sync(0xffffffffu, s, o);
    if ((tid & 31) == 0) red[tid >> 5] = s;
    __syncthreads();
    float s_all = 0.f;
#pragma unroll
    for (int w = 0; w < 8; w++) s_all += red[w];
    const float inv = 1.f / s_all;

#pragma unroll
    for (int j = 0; j < 8; j++) {
        int i = tid + j * 256;
        if (i < lenR)
            po[i] = __float2half_rn((i < len) ? v[j] * inv : 0.f);
    }
}

// ---------------------------------------------------------------------------
extern "C" void kernel_launch(void* const* d_in, const int* in_sizes, int n_in,
                              void* d_out, int out_size)
{
    const float* x = (const float*)d_in[0];
    const float* W = (const float*)d_in[1];
    float* out = (float*)d_out;

    __half *scoresh, *Ph, *xh, *xTh, *attnh, *Wh;
    cudaGetSymbolAddress((void**)&scoresh, g_scoresh);
    cudaGetSymbolAddress((void**)&Ph, g_Ph);
    cudaGetSymbolAddress((void**)&xh, g_xh);
    cudaGetSymbolAddress((void**)&xTh, g_xTh);
    cudaGetSymbolAddress((void**)&attnh, g_attnh);
    cudaGetSymbolAddress((void**)&Wh, g_Wh);

    cudaFuncSetAttribute(gemm_h,
                         cudaFuncAttributeMaxDynamicSharedMemorySize, DSMEM_SZ);

    const float scale = 1.0f / 32.0f;

    conv_x<<<dim3(SEQ / 32, DIM / 32, BATCH), 256>>>(x, xh, xTh);
    conv_W<<<(DIM * DIM / 4 + 255) / 256, 256>>>(W, Wh, (long)DIM * DIM / 4);

    // 1) scores = scale * x x^T  (fp16 out, causal tiles only)
    gemm_h<<<dim3(SEQ / TN, SEQ / TM, BATCH), 128, DSMEM_SZ>>>(
        xh, xh, scoresh, DIM, DIM, DIM, SEQ,
        (long)SEQ * DIM, (long)SEQ * DIM, (long)SEQ * SEQ,
        scale, 1, 0, 1);

    // 2) causal softmax -> fp16 P
    softmax_kernel<<<BATCH * SEQ, 256>>>(scoresh, Ph);

    // 3) attn = P x  (fp16 out, k-limited)
    gemm_h<<<dim3(DIM / TN, SEQ / TM, BATCH), 128, DSMEM_SZ>>>(
        Ph, xTh, attnh, SEQ, SEQ, SEQ, DIM,
        (long)SEQ * SEQ, (long)DIM * SEQ, (long)SEQ * DIM,
        1.0f, 0, 1, 1);

    // 4) y = attn W^T  (fp32 out)
    gemm_h<<<dim3(DIM / TN, (BATCH * SEQ) / TM, 1), 128, DSMEM_SZ>>>(
        attnh, Wh, out, DIM, DIM, DIM, DIM,
        0, 0, 0,
        1.0f, 0, 0, 0);
}